// round 2
// baseline (speedup 1.0000x reference)
#include <cuda_runtime.h>

// LCAHeavyParentLoss: BCE-with-logits sum over [B, C=11110] + greedy-path
// bottom-up cascade extras, divided by B*C.
//
// Structure (all graph-capturable, no allocations):
//   zero_acc<<<1,1>>>            : reset __device__ double accumulator
//   bce_sum_kernel<<<1184,256>>> : float4 streaming reduce of elementwise BCE
//   path_kernel<<<B/8,256>>>     : 1 warp per sample: greedy argmax walk + cascade
//   finalize<<<1,1>>>            : d_out[0] = acc / (B*C)

#define NCLS 11110
#define BRANCH 10
#define DEPTH 4

__device__ double g_acc;

__device__ __forceinline__ float bce(float x, float t) {
    // logaddexp(0,x) - x*t  ==  max(x,0) - x*t + log1p(exp(-|x|))
    return fmaxf(x, 0.0f) - x * t + log1pf(__expf(-fabsf(x)));
}

__global__ void zero_acc() { g_acc = 0.0; }

__global__ void bce_sum_kernel(const float4* __restrict__ out4,
                               const float4* __restrict__ tgt4,
                               long n4) {
    float s = 0.0f;
    long i = (long)blockIdx.x * blockDim.x + threadIdx.x;
    long stride = (long)gridDim.x * blockDim.x;
    for (; i < n4; i += stride) {
        float4 x = out4[i];
        float4 t = tgt4[i];
        s += bce(x.x, t.x) + bce(x.y, t.y) + bce(x.z, t.z) + bce(x.w, t.w);
    }
    // warp reduce
    #pragma unroll
    for (int off = 16; off; off >>= 1)
        s += __shfl_down_sync(0xffffffffu, s, off);
    __shared__ float warp_sums[8];
    int lane = threadIdx.x & 31;
    int wid  = threadIdx.x >> 5;
    if (lane == 0) warp_sums[wid] = s;
    __syncthreads();
    if (wid == 0) {
        s = (lane < (blockDim.x >> 5)) ? warp_sums[lane] : 0.0f;
        #pragma unroll
        for (int off = 4; off; off >>= 1)
            s += __shfl_down_sync(0xffffffffu, s, off);
        if (lane == 0) atomicAdd(&g_acc, (double)s);
    }
}

__global__ void path_kernel(const float* __restrict__ outputs,
                            const float* __restrict__ targets,
                            int B) {
    int warp = (blockIdx.x * blockDim.x + threadIdx.x) >> 5;
    int lane = threadIdx.x & 31;
    if (warp >= B) return;

    const float* orow = outputs + (long)warp * NCLS;

    int node = 0;
    int path[DEPTH];
    #pragma unroll
    for (int l = 0; l < DEPTH; l++) {
        float v = (lane < BRANCH) ? orow[node * BRANCH + lane] : -3.0e38f;
        int best = lane;
        // warp argmax, first-index-wins ties (matches jnp.argmax)
        #pragma unroll
        for (int off = 16; off; off >>= 1) {
            float ov = __shfl_down_sync(0xffffffffu, v, off);
            int   ob = __shfl_down_sync(0xffffffffu, best, off);
            if (ov > v || (ov == v && ob < best)) { v = ov; best = ob; }
        }
        best = __shfl_sync(0xffffffffu, best, 0);
        int edge = node * BRANCH + best;
        path[l] = edge;
        node = edge + 1;
    }

    if (lane == 0) {
        const float* trow = targets + (long)warp * NCLS;
        // Bottom-up cascade: add_l = (t_l==0) ? (L_l + add_{l+1}) : 0
        // (parent of path[l] is path[l-1] by construction). The extras are
        // the amounts added to summed entries, so total += sum of adds.
        float carry = 0.0f, extra = 0.0f;
        #pragma unroll
        for (int l = DEPTH - 1; l >= 1; --l) {
            float x = orow[path[l]];
            float t = trow[path[l]];
            float L = bce(x, t);
            float add = (t == 0.0f) ? (L + carry) : 0.0f;
            extra += add;
            carry = add;
        }
        if (extra != 0.0f) atomicAdd(&g_acc, (double)extra);
    }
}

__global__ void finalize(float* __restrict__ out, int B) {
    out[0] = (float)(g_acc / ((double)B * (double)NCLS));
}

extern "C" void kernel_launch(void* const* d_in, const int* in_sizes, int n_in,
                              void* d_out, int out_size) {
    const float* outputs = (const float*)d_in[0];
    const float* targets = (const float*)d_in[1];
    // branching / depth are fixed (10, 4) by the problem setup; hardcoded.
    int B = in_sizes[0] / NCLS;
    long n4 = (long)in_sizes[0] / 4;   // B*C divisible by 4 (22,753,280)

    zero_acc<<<1, 1>>>();
    bce_sum_kernel<<<1184, 256>>>((const float4*)outputs, (const float4*)targets, n4);
    path_kernel<<<(B * 32 + 255) / 256, 256>>>(outputs, targets, B);
    finalize<<<1, 1>>>((float*)d_out, B);
}

// round 3
// speedup vs baseline: 1.2298x; 1.2298x over previous
#include <cuda_runtime.h>

// LCAHeavyParentLoss — fully fused single kernel.
//
//   mean( BCE(outputs, targets) ) + greedy-path bottom-up cascade extras / (B*C)
//
// Key structural facts exploited:
//  * parent of path[l] is exactly path[l-1] (node_l = path[l-1]+1), so the
//    reference's descending .at[].add loop is a per-sample scan:
//      add_l = (t[path_l]==0) ? (L[path_l] + add_{l+1}) : 0 ; extras = sum add_l
//  * everything reduces to one streaming sum over 2*B*C floats (182 MB)
//    plus ~46 scattered loads per sample.
//
// Single launch: per-block partial sums -> __device__ array (overwritten each
// replay, no zeroing kernel), last block (atomic ticket) reduces partials in
// double, writes d_out[0], resets the ticket. Graph-capturable, alloc-free.

#define NCLS   11110
#define BRANCH 10
#define DEPTH  4
#define GRID_X 1184
#define BLOCK_X 256
#define NWARPS (BLOCK_X / 32)

__device__ float        g_part[GRID_X];
__device__ unsigned int g_count;   // zero at load; last block resets to 0

__device__ __forceinline__ float bce(float x, float t) {
    // max(x,0) - x*t + log1p(exp(-|x|))
    // fast path: u = expf(-|x|) in (0,1], log(1+u) via MUFU.LG2 (1+u in (1,2],
    // abs err ~2^-22 — negligible vs 1e-3 tolerance on the mean).
    float u = __expf(-fabsf(x));
    return fmaxf(x, 0.0f) - x * t + __logf(1.0f + u);
}

__global__ void __launch_bounds__(BLOCK_X)
lca_fused_kernel(const float4* __restrict__ out4,
                 const float4* __restrict__ tgt4,
                 const float*  __restrict__ outputs,
                 const float*  __restrict__ targets,
                 float* __restrict__ dout,
                 int B, long n4)
{
    const int tid  = threadIdx.x;
    const int lane = tid & 31;
    const int bid  = blockIdx.x;

    float s = 0.0f;

    // ---- fused greedy-path + cascade: first B global warps, 1 sample each ----
    {
        int gwarp = (bid * BLOCK_X + tid) >> 5;
        if (gwarp < B) {
            const float* orow = outputs + (long)gwarp * NCLS;
            int node = 0;
            int path[DEPTH];
            #pragma unroll
            for (int l = 0; l < DEPTH; l++) {
                float v = (lane < BRANCH) ? orow[node * BRANCH + lane] : -3.0e38f;
                int best = lane;
                // warp argmax, first-index-wins ties (matches jnp.argmax)
                #pragma unroll
                for (int off = 16; off; off >>= 1) {
                    float ov = __shfl_down_sync(0xffffffffu, v, off);
                    int   ob = __shfl_down_sync(0xffffffffu, best, off);
                    if (ov > v || (ov == v && ob < best)) { v = ov; best = ob; }
                }
                best = __shfl_sync(0xffffffffu, best, 0);
                int edge = node * BRANCH + best;
                path[l] = edge;
                node = edge + 1;
            }
            if (lane == 0) {
                const float* trow = targets + (long)gwarp * NCLS;
                float carry = 0.0f;
                #pragma unroll
                for (int l = DEPTH - 1; l >= 1; --l) {
                    float x = orow[path[l]];
                    float t = trow[path[l]];
                    float L = bce(x, t);
                    float add = (t == 0.0f) ? (L + carry) : 0.0f;
                    s += add;          // extras fold directly into this thread's sum
                    carry = add;
                }
            }
        }
    }

    // ---- streaming BCE sum: float4 grid-stride, unrolled for MLP ----
    {
        long i = (long)bid * BLOCK_X + tid;
        const long stride = (long)GRID_X * BLOCK_X;
        #pragma unroll 4
        for (; i < n4; i += stride) {
            float4 x = out4[i];
            float4 t = tgt4[i];
            s += bce(x.x, t.x) + bce(x.y, t.y) + bce(x.z, t.z) + bce(x.w, t.w);
        }
    }

    // ---- block reduction ----
    #pragma unroll
    for (int off = 16; off; off >>= 1)
        s += __shfl_down_sync(0xffffffffu, s, off);

    __shared__ float warp_sums[NWARPS];
    int wid = tid >> 5;
    if (lane == 0) warp_sums[wid] = s;
    __syncthreads();
    if (wid == 0) {
        s = (lane < NWARPS) ? warp_sums[lane] : 0.0f;
        #pragma unroll
        for (int off = NWARPS / 2; off; off >>= 1)
            s += __shfl_down_sync(0xffffffffu, s, off);
        if (lane == 0) g_part[bid] = s;
    }

    // ---- last-block finalize ----
    __shared__ bool is_last;
    __threadfence();
    if (tid == 0)
        is_last = (atomicAdd(&g_count, 1u) == (unsigned)(GRID_X - 1));
    __syncthreads();

    if (is_last) {
        double d = 0.0;
        for (int j = tid; j < GRID_X; j += BLOCK_X)
            d += (double)g_part[j];
        #pragma unroll
        for (int off = 16; off; off >>= 1)
            d += __shfl_down_sync(0xffffffffu, d, off);
        __shared__ double dsums[NWARPS];
        if (lane == 0) dsums[wid] = d;
        __syncthreads();
        if (wid == 0) {
            d = (lane < NWARPS) ? dsums[lane] : 0.0;
            #pragma unroll
            for (int off = NWARPS / 2; off; off >>= 1)
                d += __shfl_down_sync(0xffffffffu, d, off);
            if (lane == 0) {
                dout[0] = (float)(d / ((double)B * (double)NCLS));
                g_count = 0;   // reset ticket for next graph replay
            }
        }
    }
}

extern "C" void kernel_launch(void* const* d_in, const int* in_sizes, int n_in,
                              void* d_out, int out_size) {
    const float* outputs = (const float*)d_in[0];
    const float* targets = (const float*)d_in[1];
    int  B  = in_sizes[0] / NCLS;          // 2048
    long n4 = (long)in_sizes[0] / 4;       // B*C divisible by 4

    lca_fused_kernel<<<GRID_X, BLOCK_X>>>(
        (const float4*)outputs, (const float4*)targets,
        outputs, targets, (float*)d_out, B, n4);
}

// round 4
// speedup vs baseline: 1.2856x; 1.0453x over previous
#include <cuda_runtime.h>

// LCAHeavyParentLoss — fused single kernel, MLP-optimized stream.
//
//   mean( BCE(outputs, targets) ) + greedy-path bottom-up cascade extras / (B*C)
//
// Round-3 changes vs previous:
//  * explicit 4x unroll with front-batched loads: 8 independent LDG.128 in
//    flight per thread (MLP 2 -> 8) before any math.
//  * log amortization: sum log(1+u_i) over 16 elements = log(prod(1+u_i)),
//    prod <= 2^16 (each factor in (1,2]) — one MUFU.LG2 per 16 elements
//    instead of 16; inner loop per element is FFMA-only + one MUFU.EX2.

#define NCLS   11110
#define BRANCH 10
#define DEPTH  4
#define GRID_X 1184
#define BLOCK_X 256
#define NWARPS (BLOCK_X / 32)
#define UNROLL 4

__device__ float        g_part[GRID_X];
__device__ unsigned int g_count;   // zero at load; last block resets to 0

__device__ __forceinline__ float bce(float x, float t) {
    float u = __expf(-fabsf(x));
    return fmaxf(x, 0.0f) - x * t + __logf(1.0f + u);
}

__global__ void __launch_bounds__(BLOCK_X)
lca_fused_kernel(const float4* __restrict__ out4,
                 const float4* __restrict__ tgt4,
                 const float*  __restrict__ outputs,
                 const float*  __restrict__ targets,
                 float* __restrict__ dout,
                 int B, long n4)
{
    const int tid  = threadIdx.x;
    const int lane = tid & 31;
    const int bid  = blockIdx.x;

    float s = 0.0f;

    // ---- fused greedy-path + cascade: first B global warps, 1 sample each ----
    {
        int gwarp = (bid * BLOCK_X + tid) >> 5;
        if (gwarp < B) {
            const float* orow = outputs + (long)gwarp * NCLS;
            int node = 0;
            int path[DEPTH];
            #pragma unroll
            for (int l = 0; l < DEPTH; l++) {
                float v = (lane < BRANCH) ? orow[node * BRANCH + lane] : -3.0e38f;
                int best = lane;
                // warp argmax, first-index-wins ties (matches jnp.argmax)
                #pragma unroll
                for (int off = 16; off; off >>= 1) {
                    float ov = __shfl_down_sync(0xffffffffu, v, off);
                    int   ob = __shfl_down_sync(0xffffffffu, best, off);
                    if (ov > v || (ov == v && ob < best)) { v = ov; best = ob; }
                }
                best = __shfl_sync(0xffffffffu, best, 0);
                int edge = node * BRANCH + best;
                path[l] = edge;
                node = edge + 1;
            }
            if (lane == 0) {
                const float* trow = targets + (long)gwarp * NCLS;
                float carry = 0.0f;
                #pragma unroll
                for (int l = DEPTH - 1; l >= 1; --l) {
                    float x = orow[path[l]];
                    float t = trow[path[l]];
                    float L = bce(x, t);
                    float add = (t == 0.0f) ? (L + carry) : 0.0f;
                    s += add;          // extras fold into this thread's sum
                    carry = add;
                }
            }
        }
    }

    // ---- streaming BCE sum: 4x unrolled, front-batched float4 loads ----
    {
        const long stride = (long)GRID_X * BLOCK_X;
        long i = (long)bid * BLOCK_X + tid;

        // main: 8 independent LDG.128 per iteration, then compute
        for (; i + 3 * stride < n4; i += 4 * stride) {
            float4 x0 = out4[i];
            float4 x1 = out4[i + stride];
            float4 x2 = out4[i + 2 * stride];
            float4 x3 = out4[i + 3 * stride];
            float4 t0 = tgt4[i];
            float4 t1 = tgt4[i + stride];
            float4 t2 = tgt4[i + 2 * stride];
            float4 t3 = tgt4[i + 3 * stride];

            float xs[16] = { x0.x, x0.y, x0.z, x0.w,  x1.x, x1.y, x1.z, x1.w,
                             x2.x, x2.y, x2.z, x2.w,  x3.x, x3.y, x3.z, x3.w };
            float ts[16] = { t0.x, t0.y, t0.z, t0.w,  t1.x, t1.y, t1.z, t1.w,
                             t2.x, t2.y, t2.z, t2.w,  t3.x, t3.y, t3.z, t3.w };

            float p = 1.0f;          // prod(1 + exp(-|x|)), in (1, 2^16]
            #pragma unroll
            for (int k = 0; k < 16; k++) {
                float x = xs[k];
                float u = __expf(-fabsf(x));        // FMUL + MUFU.EX2
                p = fmaf(p, u, p);                  // p *= (1+u)
                s = fmaf(x, -ts[k], s + fmaxf(x, 0.0f));
            }
            s += __logf(p);                         // one LG2 per 16 elements
        }

        // tail
        for (; i < n4; i += stride) {
            float4 x = out4[i];
            float4 t = tgt4[i];
            s += bce(x.x, t.x) + bce(x.y, t.y) + bce(x.z, t.z) + bce(x.w, t.w);
        }
    }

    // ---- block reduction ----
    #pragma unroll
    for (int off = 16; off; off >>= 1)
        s += __shfl_down_sync(0xffffffffu, s, off);

    __shared__ float warp_sums[NWARPS];
    int wid = tid >> 5;
    if (lane == 0) warp_sums[wid] = s;
    __syncthreads();
    if (wid == 0) {
        s = (lane < NWARPS) ? warp_sums[lane] : 0.0f;
        #pragma unroll
        for (int off = NWARPS / 2; off; off >>= 1)
            s += __shfl_down_sync(0xffffffffu, s, off);
        if (lane == 0) g_part[bid] = s;
    }

    // ---- last-block finalize ----
    __shared__ bool is_last;
    __threadfence();
    if (tid == 0)
        is_last = (atomicAdd(&g_count, 1u) == (unsigned)(GRID_X - 1));
    __syncthreads();

    if (is_last) {
        double d = 0.0;
        for (int j = tid; j < GRID_X; j += BLOCK_X)
            d += (double)g_part[j];
        #pragma unroll
        for (int off = 16; off; off >>= 1)
            d += __shfl_down_sync(0xffffffffu, d, off);
        __shared__ double dsums[NWARPS];
        if (lane == 0) dsums[wid] = d;
        __syncthreads();
        if (wid == 0) {
            d = (lane < NWARPS) ? dsums[lane] : 0.0;
            #pragma unroll
            for (int off = NWARPS / 2; off; off >>= 1)
                d += __shfl_down_sync(0xffffffffu, d, off);
            if (lane == 0) {
                dout[0] = (float)(d / ((double)B * (double)NCLS));
                g_count = 0;   // reset ticket for next graph replay
            }
        }
    }
}

extern "C" void kernel_launch(void* const* d_in, const int* in_sizes, int n_in,
                              void* d_out, int out_size) {
    const float* outputs = (const float*)d_in[0];
    const float* targets = (const float*)d_in[1];
    int  B  = in_sizes[0] / NCLS;          // 2048
    long n4 = (long)in_sizes[0] / 4;       // B*C divisible by 4

    lca_fused_kernel<<<GRID_X, BLOCK_X>>>(
        (const float4*)outputs, (const float4*)targets,
        outputs, targets, (float*)d_out, B, n4);
}